// round 1
// baseline (speedup 1.0000x reference)
#include <cuda_runtime.h>
#include <cuda_bf16.h>
#include <math.h>

// Problem constants
#define BB    2
#define SS    2048
#define HIDD  2048
#define NHQ   16
#define NHKV  4
#define HDIM  128
#define KD    2048        // inner dim of all projections
#define MTOT  (BB*SS)     // 4096

// Scratch (device globals; allocation-free rule)
__device__ float g_q[(size_t)BB*NHQ *SS*HDIM];   // [B][H][S][HD]
__device__ float g_k[(size_t)BB*NHKV*SS*HDIM];   // [B][KVH][S][HD]
__device__ float g_v[(size_t)BB*NHKV*SS*HDIM];
__device__ float g_y[(size_t)BB*SS*HIDD];        // [B][S][HID] attn out

// ---------------------------------------------------------------------------
// SGEMM: C[m,n] = sum_k A[m,k] * W[n,k]   (both row-major, K contiguous)
// BM=BN=128, BK=16, 256 threads, 8x8 micro-tile.
// MODE: 0 = plain store to out[m*2048+n]
//       1 = head-split store ( [B][NH][S][HD] ), no rope   (V)
//       2 = head-split store + RoPE                        (Q, K)
// SRC:  0 = A param, 1 = read from g_y
// DST:  0 = g_q, 1 = g_k, 2 = g_v, 3 = out param
// ---------------------------------------------------------------------------
template<int MODE, int NH, int SRC, int DST>
__global__ __launch_bounds__(256, 2)
void proj_kernel(const float* __restrict__ Ain, const float* __restrict__ W,
                 float* __restrict__ out_param,
                 const float* __restrict__ cosb, const float* __restrict__ sinb)
{
    __shared__ float As[16][128];
    __shared__ float Bs[16][128];

    const float* __restrict__ A = (SRC == 0) ? Ain : (const float*)g_y;
    float* __restrict__ outp =
        (DST == 0) ? g_q : (DST == 1) ? g_k : (DST == 2) ? g_v : out_param;

    const int tid = threadIdx.x;
    const int tx = tid & 15, ty = tid >> 4;
    const int m0 = blockIdx.y * 128;
    const int n0 = blockIdx.x * 128;

    float acc[8][8];
#pragma unroll
    for (int i = 0; i < 8; i++)
#pragma unroll
        for (int j = 0; j < 8; j++) acc[i][j] = 0.f;

    for (int k0 = 0; k0 < KD; k0 += 16) {
#pragma unroll
        for (int u = 0; u < 2; u++) {
            int idx = tid * 2 + u;               // 0..511
            int row = idx >> 2;                  // 0..127
            int c4  = (idx & 3) * 4;             // 0,4,8,12
            float4 av = *(const float4*)(A + (size_t)(m0 + row) * KD + k0 + c4);
            As[c4 + 0][row] = av.x; As[c4 + 1][row] = av.y;
            As[c4 + 2][row] = av.z; As[c4 + 3][row] = av.w;
            float4 wv = *(const float4*)(W + (size_t)(n0 + row) * KD + k0 + c4);
            Bs[c4 + 0][row] = wv.x; Bs[c4 + 1][row] = wv.y;
            Bs[c4 + 2][row] = wv.z; Bs[c4 + 3][row] = wv.w;
        }
        __syncthreads();
#pragma unroll
        for (int kk = 0; kk < 16; kk++) {
            float a[8], b[8];
            *(float4*)&a[0] = *(const float4*)&As[kk][ty * 4];
            *(float4*)&a[4] = *(const float4*)&As[kk][64 + ty * 4];
            *(float4*)&b[0] = *(const float4*)&Bs[kk][tx * 4];
            *(float4*)&b[4] = *(const float4*)&Bs[kk][64 + tx * 4];
#pragma unroll
            for (int i = 0; i < 8; i++)
#pragma unroll
                for (int j = 0; j < 8; j++) acc[i][j] = fmaf(a[i], b[j], acc[i][j]);
        }
        __syncthreads();
    }

    // Epilogue
#pragma unroll
    for (int i = 0; i < 8; i++) {
        int m = m0 + ((i < 4) ? (ty * 4 + i) : (64 + ty * 4 + i - 4));
        int bidx = m / SS;
        int s    = m % SS;
        if (MODE == 0) {
            int n = n0 + tx * 4;
            *(float4*)(outp + (size_t)m * 2048 + n)      = *(float4*)&acc[i][0];
            *(float4*)(outp + (size_t)m * 2048 + n + 64) = *(float4*)&acc[i][4];
        } else {
#pragma unroll
            for (int jj = 0; jj < 8; jj += 2) {
                int n = n0 + ((jj < 4) ? (tx * 4 + jj) : (64 + tx * 4 + jj - 4));
                float e = acc[i][jj], o = acc[i][jj + 1];
                float oe, oo;
                if (MODE == 2) {
                    int f = (n & (HDIM - 1)) >> 1;
                    float c  = cosb[s * (HDIM / 2) + f];
                    float sn = sinb[s * (HDIM / 2) + f];
                    oe = e * c - o * sn;
                    oo = e * sn + o * c;
                } else {
                    oe = e; oo = o;
                }
                int h = n >> 7;          // n / HDIM
                int d = n & (HDIM - 1);
                float2 st = make_float2(oe, oo);
                *(float2*)(outp + ((((size_t)bidx * NH + h) * SS + s) * HDIM + d)) = st;
            }
        }
    }
}

// ---------------------------------------------------------------------------
// Flash attention, fp32, causal, GQA (16 q-heads over 4 kv-heads)
// BQ = BK = 64, D = 128, 256 threads.
//   score micro-tile: 4 rows x 4 cols per thread (16x16 thread grid)
//   PV micro-tile:    4 rows x 8 dims per thread
// ---------------------------------------------------------------------------
#define FL_QST   0                       // QsT[128][68] transposed (d-major)
#define FL_KS    (128*68)                // Ks[64][133] natural
#define FL_VS    (FL_KS + 64*133)        // Vs[64][132] natural
#define FL_PST   (FL_VS + 64*132)        // PsT[64][68] transposed (k-major)
#define FL_M     (FL_PST + 64*68)
#define FL_L     (FL_M + 64)
#define FL_SC    (FL_L + 64)
#define FL_TOTAL (FL_SC + 64)            // floats
#define FLASH_SMEM_BYTES (FL_TOTAL * 4)  // 120832 B

__global__ __launch_bounds__(256, 1)
void flash_kernel()
{
    extern __shared__ float sm[];
    float* QsT   = sm + FL_QST;
    float* Ks    = sm + FL_KS;
    float* Vs    = sm + FL_VS;
    float* PsT   = sm + FL_PST;
    float* m_sh  = sm + FL_M;
    float* l_sh  = sm + FL_L;
    float* sc_sh = sm + FL_SC;

    const int tid  = threadIdx.x;
    const int trow = tid >> 4;           // 0..15
    const int tcol = tid & 15;           // 0..15
    const int r0   = trow * 4;           // rows 0..63
    const int kc0  = tcol * 4;           // score cols
    const int d0   = tcol * 8;           // PV dims

    const int qt = blockIdx.x;           // q tile
    const int h  = blockIdx.y;
    const int b  = blockIdx.z;
    const int q0 = qt * 64;
    const int kvh = h / (NHQ / NHKV);
    const float scale = 0.08838834764831845f;   // 1/sqrt(128)

    const float* Qg = g_q + (((size_t)b * NHQ + h) * SS + q0) * HDIM;
    const float* Kb = g_k + (((size_t)b * NHKV + kvh) * SS) * HDIM;
    const float* Vb = g_v + (((size_t)b * NHKV + kvh) * SS) * HDIM;

    // Load Q tile transposed + pre-scale
    for (int i = tid; i < 64 * 32; i += 256) {
        int row = i >> 5, c4 = (i & 31) * 4;
        float4 qv = *(const float4*)(Qg + row * HDIM + c4);
        QsT[(c4 + 0) * 68 + row] = qv.x * scale;
        QsT[(c4 + 1) * 68 + row] = qv.y * scale;
        QsT[(c4 + 2) * 68 + row] = qv.z * scale;
        QsT[(c4 + 3) * 68 + row] = qv.w * scale;
    }
    if (tid < 64) { m_sh[tid] = -1e30f; l_sh[tid] = 0.f; }

    float acc[4][8];
#pragma unroll
    for (int i = 0; i < 4; i++)
#pragma unroll
        for (int j = 0; j < 8; j++) acc[i][j] = 0.f;

    const int ntiles = qt + 1;
    for (int t = 0; t < ntiles; ++t) {
        const int k0 = t * 64;
        __syncthreads();   // protect Ks/Vs/PsT from previous iteration readers
        // Load K (scalar stores, stride 133) and V (float4, stride 132)
        const float* Kg = Kb + (size_t)k0 * HDIM;
        const float* Vg = Vb + (size_t)k0 * HDIM;
        for (int i = tid; i < 64 * 32; i += 256) {
            int row = i >> 5, c4 = (i & 31) * 4;
            float4 kv = *(const float4*)(Kg + row * HDIM + c4);
            float* kd = &Ks[row * 133 + c4];
            kd[0] = kv.x; kd[1] = kv.y; kd[2] = kv.z; kd[3] = kv.w;
            float4 vv = *(const float4*)(Vg + row * HDIM + c4);
            *(float4*)&Vs[row * 132 + c4] = vv;
        }
        __syncthreads();

        // Scores: S[r0..r0+3][kc0..kc0+3]
        float sv[4][4];
#pragma unroll
        for (int i = 0; i < 4; i++)
#pragma unroll
            for (int j = 0; j < 4; j++) sv[i][j] = 0.f;

#pragma unroll 4
        for (int d = 0; d < 128; d++) {
            float4 a = *(const float4*)(QsT + d * 68 + r0);
            float b0 = Ks[(kc0 + 0) * 133 + d];
            float b1 = Ks[(kc0 + 1) * 133 + d];
            float b2 = Ks[(kc0 + 2) * 133 + d];
            float b3 = Ks[(kc0 + 3) * 133 + d];
            sv[0][0] = fmaf(a.x, b0, sv[0][0]); sv[0][1] = fmaf(a.x, b1, sv[0][1]);
            sv[0][2] = fmaf(a.x, b2, sv[0][2]); sv[0][3] = fmaf(a.x, b3, sv[0][3]);
            sv[1][0] = fmaf(a.y, b0, sv[1][0]); sv[1][1] = fmaf(a.y, b1, sv[1][1]);
            sv[1][2] = fmaf(a.y, b2, sv[1][2]); sv[1][3] = fmaf(a.y, b3, sv[1][3]);
            sv[2][0] = fmaf(a.z, b0, sv[2][0]); sv[2][1] = fmaf(a.z, b1, sv[2][1]);
            sv[2][2] = fmaf(a.z, b2, sv[2][2]); sv[2][3] = fmaf(a.z, b3, sv[2][3]);
            sv[3][0] = fmaf(a.w, b0, sv[3][0]); sv[3][1] = fmaf(a.w, b1, sv[3][1]);
            sv[3][2] = fmaf(a.w, b2, sv[3][2]); sv[3][3] = fmaf(a.w, b3, sv[3][3]);
        }

        // Causal mask on diagonal tile
        if (t == qt) {
#pragma unroll
            for (int i = 0; i < 4; i++)
#pragma unroll
                for (int j = 0; j < 4; j++)
                    if (k0 + kc0 + j > q0 + r0 + i) sv[i][j] = -1e30f;
        }

        // Store transposed
#pragma unroll
        for (int j = 0; j < 4; j++)
#pragma unroll
            for (int i = 0; i < 4; i++)
                PsT[(kc0 + j) * 68 + r0 + i] = sv[i][j];
        __syncthreads();

        // Online softmax: 4 threads per row
        {
            int r = tid >> 2, seg = tid & 3;
            float vals[16];
            float mloc = -1e30f;
#pragma unroll
            for (int u = 0; u < 16; u++) {
                vals[u] = PsT[(seg * 16 + u) * 68 + r];
                mloc = fmaxf(mloc, vals[u]);
            }
            mloc = fmaxf(mloc, __shfl_xor_sync(0xffffffffu, mloc, 1));
            mloc = fmaxf(mloc, __shfl_xor_sync(0xffffffffu, mloc, 2));
            float m_old = m_sh[r];
            float m_new = fmaxf(m_old, mloc);
            float sum = 0.f;
#pragma unroll
            for (int u = 0; u < 16; u++) {
                float p = __expf(vals[u] - m_new);
                PsT[(seg * 16 + u) * 68 + r] = p;
                sum += p;
            }
            sum += __shfl_xor_sync(0xffffffffu, sum, 1);
            sum += __shfl_xor_sync(0xffffffffu, sum, 2);
            if (seg == 0) {
                float scl = __expf(m_old - m_new);
                m_sh[r]  = m_new;
                l_sh[r]  = l_sh[r] * scl + sum;
                sc_sh[r] = scl;
            }
        }
        __syncthreads();

        // Rescale + PV accumulate
        {
            float scl[4];
#pragma unroll
            for (int i = 0; i < 4; i++) scl[i] = sc_sh[r0 + i];
#pragma unroll
            for (int i = 0; i < 4; i++)
#pragma unroll
                for (int j = 0; j < 8; j++) acc[i][j] *= scl[i];

#pragma unroll 4
            for (int kk = 0; kk < 64; kk++) {
                float4 a  = *(const float4*)(PsT + kk * 68 + r0);
                float4 v0 = *(const float4*)(Vs + kk * 132 + d0);
                float4 v1 = *(const float4*)(Vs + kk * 132 + d0 + 4);
                float bv[8] = {v0.x, v0.y, v0.z, v0.w, v1.x, v1.y, v1.z, v1.w};
                float av[4] = {a.x, a.y, a.z, a.w};
#pragma unroll
                for (int i = 0; i < 4; i++)
#pragma unroll
                    for (int j = 0; j < 8; j++)
                        acc[i][j] = fmaf(av[i], bv[j], acc[i][j]);
            }
        }
    }

    // Epilogue: normalize and write to g_y [B][S][HID]
#pragma unroll
    for (int i = 0; i < 4; i++) {
        int r = r0 + i;
        float inv = 1.f / l_sh[r];
        float4 o0 = make_float4(acc[i][0]*inv, acc[i][1]*inv, acc[i][2]*inv, acc[i][3]*inv);
        float4 o1 = make_float4(acc[i][4]*inv, acc[i][5]*inv, acc[i][6]*inv, acc[i][7]*inv);
        float* op = g_y + ((size_t)b * SS + q0 + r) * HIDD + h * HDIM + d0;
        *(float4*)op       = o0;
        *(float4*)(op + 4) = o1;
    }
}

// ---------------------------------------------------------------------------
extern "C" void kernel_launch(void* const* d_in, const int* in_sizes, int n_in,
                              void* d_out, int out_size)
{
    const float* x    = (const float*)d_in[0];
    const float* cosb = (const float*)d_in[1];
    const float* sinb = (const float*)d_in[2];
    const float* Wq   = (const float*)d_in[3];
    const float* Wk   = (const float*)d_in[4];
    const float* Wv   = (const float*)d_in[5];
    const float* Wo   = (const float*)d_in[6];
    float* out = (float*)d_out;

    cudaFuncSetAttribute(flash_kernel,
                         cudaFuncAttributeMaxDynamicSharedMemorySize,
                         FLASH_SMEM_BYTES);

    dim3 blk(256);
    // Q projection + RoPE  (N = 2048)
    proj_kernel<2, NHQ, 0, 0><<<dim3(16, 32), blk>>>(x, Wq, nullptr, cosb, sinb);
    // K projection + RoPE  (N = 512)
    proj_kernel<2, NHKV, 0, 1><<<dim3(4, 32), blk>>>(x, Wk, nullptr, cosb, sinb);
    // V projection         (N = 512)
    proj_kernel<1, NHKV, 0, 2><<<dim3(4, 32), blk>>>(x, Wv, nullptr, nullptr, nullptr);
    // Flash attention
    flash_kernel<<<dim3(SS / 64, NHQ, BB), 256, FLASH_SMEM_BYTES>>>();
    // Output projection (N = 2048), reads g_y, writes d_out
    proj_kernel<0, 1, 1, 3><<<dim3(16, 32), blk>>>(nullptr, Wo, out, nullptr, nullptr);
}

// round 3
// speedup vs baseline: 1.0126x; 1.0126x over previous
#include <cuda_runtime.h>
#include <cuda_bf16.h>
#include <math.h>
#include <stdint.h>

// Problem constants
#define BB    2
#define SS    2048
#define HIDD  2048
#define NHQ   16
#define NHKV  4
#define HDIM  128
#define KD    2048
#define MTOT  (BB*SS)     // 4096

// ---------------------------------------------------------------------------
// Device-global scratch (allocation-free rule)
// ---------------------------------------------------------------------------
__device__ float g_q[(size_t)BB*NHQ *SS*HDIM];   // [B][H][S][HD]
__device__ float g_k[(size_t)BB*NHKV*SS*HDIM];
__device__ float g_v[(size_t)BB*NHKV*SS*HDIM];
__device__ float g_y[(size_t)BB*SS*HIDD];        // attn out [B][S][HID]

// split-bf16 operands
__device__ __nv_bfloat16 g_xh[(size_t)MTOT*KD];
__device__ __nv_bfloat16 g_xl[(size_t)MTOT*KD];
__device__ __nv_bfloat16 g_wqh[(size_t)2048*2048], g_wql[(size_t)2048*2048];
__device__ __nv_bfloat16 g_wkh[(size_t)512*2048],  g_wkl[(size_t)512*2048];
__device__ __nv_bfloat16 g_wvh[(size_t)512*2048],  g_wvl[(size_t)512*2048];
__device__ __nv_bfloat16 g_woh[(size_t)2048*2048], g_wol[(size_t)2048*2048];

// ---------------------------------------------------------------------------
__device__ __forceinline__ uint32_t smem_u32(const void* p) {
    uint32_t a;
    asm("{ .reg .u64 t; cvta.to.shared.u64 t, %1; cvt.u32.u64 %0, t; }"
        : "=r"(a) : "l"(p));
    return a;
}

#define LDM4(r0, r1, r2, r3, addr) \
    asm volatile("ldmatrix.sync.aligned.m8n8.x4.shared.b16 {%0,%1,%2,%3}, [%4];" \
                 : "=r"(r0), "=r"(r1), "=r"(r2), "=r"(r3) : "r"(addr))

#define MMA16816(acc, a, b) \
    asm volatile("mma.sync.aligned.m16n8k16.row.col.f32.bf16.bf16.f32 " \
                 "{%0,%1,%2,%3},{%4,%5,%6,%7},{%8,%9},{%0,%1,%2,%3};" \
                 : "+f"((acc)[0]), "+f"((acc)[1]), "+f"((acc)[2]), "+f"((acc)[3]) \
                 : "r"((a)[0]), "r"((a)[1]), "r"((a)[2]), "r"((a)[3]), \
                   "r"((b)[0]), "r"((b)[1]))

// swizzled byte offset within an 8KB tile: 128 rows x 64B, chunk = 16B unit
__device__ __forceinline__ uint32_t tile_off(int row, int chunk) {
    return (uint32_t)(row * 64 + ((chunk ^ ((row >> 1) & 3)) << 4));
}

// ---------------------------------------------------------------------------
// fp32 -> split bf16 (hi/lo)
// DST: 0=x, 1=Wq, 2=Wk, 3=Wv, 4=Wo, 5=g_y
// ---------------------------------------------------------------------------
template<int DST>
__global__ void cvt_kernel(const float* __restrict__ srcp, int n4)
{
    int i = blockIdx.x * 256 + threadIdx.x;
    if (i >= n4) return;
    const float4* s4 = (DST == 5) ? (const float4*)g_y : (const float4*)srcp;
    __nv_bfloat16* hi =
        (DST == 0 || DST == 5) ? g_xh : (DST == 1) ? g_wqh :
        (DST == 2) ? g_wkh : (DST == 3) ? g_wvh : g_woh;
    __nv_bfloat16* lo =
        (DST == 0 || DST == 5) ? g_xl : (DST == 1) ? g_wql :
        (DST == 2) ? g_wkl : (DST == 3) ? g_wvl : g_wol;
    float4 v = s4[i];
    __nv_bfloat16 hx = __float2bfloat16(v.x);
    __nv_bfloat16 hy = __float2bfloat16(v.y);
    __nv_bfloat16 hz = __float2bfloat16(v.z);
    __nv_bfloat16 hw = __float2bfloat16(v.w);
    __nv_bfloat16 lx = __float2bfloat16(v.x - __bfloat162float(hx));
    __nv_bfloat16 ly = __float2bfloat16(v.y - __bfloat162float(hy));
    __nv_bfloat16 lz = __float2bfloat16(v.z - __bfloat162float(hz));
    __nv_bfloat16 lw = __float2bfloat16(v.w - __bfloat162float(hw));
    ((__nv_bfloat162*)hi)[2 * i]     = __halves2bfloat162(hx, hy);
    ((__nv_bfloat162*)hi)[2 * i + 1] = __halves2bfloat162(hz, hw);
    ((__nv_bfloat162*)lo)[2 * i]     = __halves2bfloat162(lx, ly);
    ((__nv_bfloat162*)lo)[2 * i + 1] = __halves2bfloat162(lz, lw);
}

// ---------------------------------------------------------------------------
// mma.sync split-bf16 GEMM: C[128x128] = A[M,K] * W[N,K]^T (3 passes)
// 8 warps (2m x 4n), warp tile 64x32, BK=32, double-buffered cp.async.
// MODE: 0 plain store; 1 head-split; 2 head-split + RoPE
// ---------------------------------------------------------------------------
#define GEMM_SMEM 65536   // 2 stages x (4 tiles x 8KB)

template<int MODE, int NH, int WSEL, int DST>
__global__ __launch_bounds__(256, 1)
void gemm_mma(float* __restrict__ out_param,
              const float* __restrict__ cosb, const float* __restrict__ sinb)
{
    extern __shared__ __align__(128) char smem[];
    const uint32_t sb = smem_u32(smem);
    const int tid = threadIdx.x, wid = tid >> 5, lane = tid & 31;
    const int m0 = blockIdx.y * 128, n0 = blockIdx.x * 128;
    const int m_base = (wid & 1) * 64;
    const int n_base = (wid >> 1) * 32;

    const __nv_bfloat16* Ah = g_xh;
    const __nv_bfloat16* Al = g_xl;
    const __nv_bfloat16* Wh =
        (WSEL == 0) ? g_wqh : (WSEL == 1) ? g_wkh : (WSEL == 2) ? g_wvh : g_woh;
    const __nv_bfloat16* Wl =
        (WSEL == 0) ? g_wql : (WSEL == 1) ? g_wkl : (WSEL == 2) ? g_wvl : g_wol;
    float* outp = (DST == 0) ? g_q : (DST == 1) ? g_k : (DST == 2) ? g_v : out_param;

    float acc[4][4][4];
#pragma unroll
    for (int mi = 0; mi < 4; mi++)
#pragma unroll
        for (int ni = 0; ni < 4; ni++)
#pragma unroll
            for (int q = 0; q < 4; q++) acc[mi][ni][q] = 0.f;

    // per-thread load slots: 8 x 16B; slot s -> tile=(s>>1), row/chunk from rem
    auto load_stage = [&](int stage, int k0) {
        uint32_t sbase = sb + stage * 32768;
#pragma unroll
        for (int s = 0; s < 8; s++) {
            int idx  = s * 256 + tid;       // 0..2047
            int tile = idx >> 9;            // 0..3
            int rem  = idx & 511;
            int row  = rem >> 2, ch = rem & 3;
            const __nv_bfloat16* src =
                (tile == 0) ? Ah : (tile == 1) ? Al : (tile == 2) ? Wh : Wl;
            int grow = ((tile < 2) ? m0 : n0) + row;
            const __nv_bfloat16* g = src + (size_t)grow * KD + k0 + ch * 8;
            uint32_t d = sbase + tile * 8192 + tile_off(row, ch);
            asm volatile("cp.async.cg.shared.global [%0], [%1], 16;"
                         :: "r"(d), "l"(g) : "memory");
        }
        asm volatile("cp.async.commit_group;" ::: "memory");
    };

    load_stage(0, 0);

    const int l15 = lane & 15, lh = lane >> 4;     // A-frag addressing
    const int bmat = lane >> 3, br = lane & 7;     // B-frag addressing

    for (int c = 0; c < 64; c++) {
        if (c < 63) {
            load_stage((c + 1) & 1, (c + 1) * 32);
            asm volatile("cp.async.wait_group 1;" ::: "memory");
        } else {
            asm volatile("cp.async.wait_group 0;" ::: "memory");
        }
        __syncthreads();

        uint32_t stg = sb + (c & 1) * 32768;
        uint32_t tAh = stg, tAl = stg + 8192, tWh = stg + 16384, tWl = stg + 24576;

#pragma unroll
        for (int ks = 0; ks < 2; ks++) {
            int kc = ks * 2;
            uint32_t ah[4][4], al[4][4], whf[4][2], wlf[4][2];
#pragma unroll
            for (int mi = 0; mi < 4; mi++) {
                int row = m_base + mi * 16 + l15;
                uint32_t o = tile_off(row, kc + lh);
                LDM4(ah[mi][0], ah[mi][1], ah[mi][2], ah[mi][3], tAh + o);
                LDM4(al[mi][0], al[mi][1], al[mi][2], al[mi][3], tAl + o);
            }
#pragma unroll
            for (int ng = 0; ng < 2; ng++) {
                int row = n_base + ng * 16 + ((bmat & 2) << 2) + br;
                uint32_t o = tile_off(row, kc + (bmat & 1));
                uint32_t r0, r1, r2, r3;
                LDM4(r0, r1, r2, r3, tWh + o);
                whf[ng * 2][0] = r0;     whf[ng * 2][1] = r1;
                whf[ng * 2 + 1][0] = r2; whf[ng * 2 + 1][1] = r3;
                LDM4(r0, r1, r2, r3, tWl + o);
                wlf[ng * 2][0] = r0;     wlf[ng * 2][1] = r1;
                wlf[ng * 2 + 1][0] = r2; wlf[ng * 2 + 1][1] = r3;
            }
#pragma unroll
            for (int mi = 0; mi < 4; mi++)
#pragma unroll
                for (int ni = 0; ni < 4; ni++) {
                    MMA16816(acc[mi][ni], ah[mi], whf[ni]);
                    MMA16816(acc[mi][ni], ah[mi], wlf[ni]);
                    MMA16816(acc[mi][ni], al[mi], whf[ni]);
                }
        }
        __syncthreads();
    }

    // Epilogue from C fragments
    const int tr = lane >> 2, tc = lane & 3;
#pragma unroll
    for (int mi = 0; mi < 4; mi++) {
#pragma unroll
        for (int ni = 0; ni < 4; ni++) {
            int ncol = n0 + n_base + ni * 8 + tc * 2;
#pragma unroll
            for (int half = 0; half < 2; half++) {
                int m = m0 + m_base + mi * 16 + tr + half * 8;
                float e = acc[mi][ni][half * 2];
                float o = acc[mi][ni][half * 2 + 1];
                if (MODE == 0) {
                    *(float2*)(outp + (size_t)m * 2048 + ncol) = make_float2(e, o);
                } else {
                    int bb = m >> 11, s = m & 2047;
                    float oe, oo;
                    if (MODE == 2) {
                        int f = (ncol & (HDIM - 1)) >> 1;
                        float cs = cosb[s * 64 + f];
                        float sn = sinb[s * 64 + f];
                        oe = e * cs - o * sn;
                        oo = e * sn + o * cs;
                    } else { oe = e; oo = o; }
                    int h = ncol >> 7, d = ncol & (HDIM - 1);
                    *(float2*)(outp + (((size_t)bb * NH + h) * SS + s) * HDIM + d) =
                        make_float2(oe, oo);
                }
            }
        }
    }
}

// ---------------------------------------------------------------------------
// Flash attention, fp32, causal, GQA — unchanged (known correct)
// ---------------------------------------------------------------------------
#define FL_QST   0
#define FL_KS    (128*68)
#define FL_VS    (FL_KS + 64*133)
#define FL_PST   (FL_VS + 64*132)
#define FL_M     (FL_PST + 64*68)
#define FL_L     (FL_M + 64)
#define FL_SC    (FL_L + 64)
#define FL_TOTAL (FL_SC + 64)
#define FLASH_SMEM_BYTES (FL_TOTAL * 4)

__global__ __launch_bounds__(256, 1)
void flash_kernel()
{
    extern __shared__ float sm[];
    float* QsT   = sm + FL_QST;
    float* Ks    = sm + FL_KS;
    float* Vs    = sm + FL_VS;
    float* PsT   = sm + FL_PST;
    float* m_sh  = sm + FL_M;
    float* l_sh  = sm + FL_L;
    float* sc_sh = sm + FL_SC;

    const int tid  = threadIdx.x;
    const int trow = tid >> 4;
    const int tcol = tid & 15;
    const int r0   = trow * 4;
    const int kc0  = tcol * 4;
    const int d0   = tcol * 8;

    const int qt = blockIdx.x;
    const int h  = blockIdx.y;
    const int b  = blockIdx.z;
    const int q0 = qt * 64;
    const int kvh = h / (NHQ / NHKV);
    const float scale = 0.08838834764831845f;

    const float* Qg = g_q + (((size_t)b * NHQ + h) * SS + q0) * HDIM;
    const float* Kb = g_k + (((size_t)b * NHKV + kvh) * SS) * HDIM;
    const float* Vb = g_v + (((size_t)b * NHKV + kvh) * SS) * HDIM;

    for (int i = tid; i < 64 * 32; i += 256) {
        int row = i >> 5, c4 = (i & 31) * 4;
        float4 qv = *(const float4*)(Qg + row * HDIM + c4);
        QsT[(c4 + 0) * 68 + row] = qv.x * scale;
        QsT[(c4 + 1) * 68 + row] = qv.y * scale;
        QsT[(c4 + 2) * 68 + row] = qv.z * scale;
        QsT[(c4 + 3) * 68 + row] = qv.w * scale;
    }
    if (tid < 64) { m_sh[tid] = -1e30f; l_sh[tid] = 0.f; }

    float acc[4][8];
#pragma unroll
    for (int i = 0; i < 4; i++)
#pragma unroll
        for (int j = 0; j < 8; j++) acc[i][j] = 0.f;

    const int ntiles = qt + 1;
    for (int t = 0; t < ntiles; ++t) {
        const int k0 = t * 64;
        __syncthreads();
        const float* Kg = Kb + (size_t)k0 * HDIM;
        const float* Vg = Vb + (size_t)k0 * HDIM;
        for (int i = tid; i < 64 * 32; i += 256) {
            int row = i >> 5, c4 = (i & 31) * 4;
            float4 kv = *(const float4*)(Kg + row * HDIM + c4);
            float* kd = &Ks[row * 133 + c4];
            kd[0] = kv.x; kd[1] = kv.y; kd[2] = kv.z; kd[3] = kv.w;
            float4 vv = *(const float4*)(Vg + row * HDIM + c4);
            *(float4*)&Vs[row * 132 + c4] = vv;
        }
        __syncthreads();

        float sv[4][4];
#pragma unroll
        for (int i = 0; i < 4; i++)
#pragma unroll
            for (int j = 0; j < 4; j++) sv[i][j] = 0.f;

#pragma unroll 4
        for (int d = 0; d < 128; d++) {
            float4 a = *(const float4*)(QsT + d * 68 + r0);
            float b0 = Ks[(kc0 + 0) * 133 + d];
            float b1 = Ks[(kc0 + 1) * 133 + d];
            float b2 = Ks[(kc0 + 2) * 133 + d];
            float b3 = Ks[(kc0 + 3) * 133 + d];
            sv[0][0] = fmaf(a.x, b0, sv[0][0]); sv[0][1] = fmaf(a.x, b1, sv[0][1]);
            sv[0][2] = fmaf(a.x, b2, sv[0][2]); sv[0][3] = fmaf(a.x, b3, sv[0][3]);
            sv[1][0] = fmaf(a.y, b0, sv[1][0]); sv[1][1] = fmaf(a.y, b1, sv[1][1]);
            sv[1][2] = fmaf(a.y, b2, sv[1][2]); sv[1][3] = fmaf(a.y, b3, sv[1][3]);
            sv[2][0] = fmaf(a.z, b0, sv[2][0]); sv[2][1] = fmaf(a.z, b1, sv[2][1]);
            sv[2][2] = fmaf(a.z, b2, sv[2][2]); sv[2][3] = fmaf(a.z, b3, sv[2][3]);
            sv[3][0] = fmaf(a.w, b0, sv[3][0]); sv[3][1] = fmaf(a.w, b1, sv[3][1]);
            sv[3][2] = fmaf(a.w, b2, sv[3][2]); sv[3][3] = fmaf(a.w, b3, sv[3][3]);
        }

        if (t == qt) {
#pragma unroll
            for (int i = 0; i < 4; i++)
#pragma unroll
                for (int j = 0; j < 4; j++)
                    if (k0 + kc0 + j > q0 + r0 + i) sv[i][j] = -1e30f;
        }

#pragma unroll
        for (int j = 0; j < 4; j++)
#pragma unroll
            for (int i = 0; i < 4; i++)
                PsT[(kc0 + j) * 68 + r0 + i] = sv[i][j];
        __syncthreads();

        {
            int r = tid >> 2, seg = tid & 3;
            float vals[16];
            float mloc = -1e30f;
#pragma unroll
            for (int u = 0; u < 16; u++) {
                vals[u] = PsT[(seg * 16 + u) * 68 + r];
                mloc = fmaxf(mloc, vals[u]);
            }
            mloc = fmaxf(mloc, __shfl_xor_sync(0xffffffffu, mloc, 1));
            mloc = fmaxf(mloc, __shfl_xor_sync(0xffffffffu, mloc, 2));
            float m_old = m_sh[r];
            float m_new = fmaxf(m_old, mloc);
            float sum = 0.f;
#pragma unroll
            for (int u = 0; u < 16; u++) {
                float p = __expf(vals[u] - m_new);
                PsT[(seg * 16 + u) * 68 + r] = p;
                sum += p;
            }
            sum += __shfl_xor_sync(0xffffffffu, sum, 1);
            sum += __shfl_xor_sync(0xffffffffu, sum, 2);
            if (seg == 0) {
                float scl = __expf(m_old - m_new);
                m_sh[r]  = m_new;
                l_sh[r]  = l_sh[r] * scl + sum;
                sc_sh[r] = scl;
            }
        }
        __syncthreads();

        {
            float scl[4];
#pragma unroll
            for (int i = 0; i < 4; i++) scl[i] = sc_sh[r0 + i];
#pragma unroll
            for (int i = 0; i < 4; i++)
#pragma unroll
                for (int j = 0; j < 8; j++) acc[i][j] *= scl[i];

#pragma unroll 4
            for (int kk = 0; kk < 64; kk++) {
                float4 a  = *(const float4*)(PsT + kk * 68 + r0);
                float4 v0 = *(const float4*)(Vs + kk * 132 + d0);
                float4 v1 = *(const float4*)(Vs + kk * 132 + d0 + 4);
                float bv[8] = {v0.x, v0.y, v0.z, v0.w, v1.x, v1.y, v1.z, v1.w};
                float av[4] = {a.x, a.y, a.z, a.w};
#pragma unroll
                for (int i = 0; i < 4; i++)
#pragma unroll
                    for (int j = 0; j < 8; j++)
                        acc[i][j] = fmaf(av[i], bv[j], acc[i][j]);
            }
        }
    }

#pragma unroll
    for (int i = 0; i < 4; i++) {
        int r = r0 + i;
        float inv = 1.f / l_sh[r];
        float4 o0 = make_float4(acc[i][0]*inv, acc[i][1]*inv, acc[i][2]*inv, acc[i][3]*inv);
        float4 o1 = make_float4(acc[i][4]*inv, acc[i][5]*inv, acc[i][6]*inv, acc[i][7]*inv);
        float* op = g_y + ((size_t)b * SS + q0 + r) * HIDD + h * HDIM + d0;
        *(float4*)op       = o0;
        *(float4*)(op + 4) = o1;
    }
}

// ---------------------------------------------------------------------------
extern "C" void kernel_launch(void* const* d_in, const int* in_sizes, int n_in,
                              void* d_out, int out_size)
{
    const float* x    = (const float*)d_in[0];
    const float* cosb = (const float*)d_in[1];
    const float* sinb = (const float*)d_in[2];
    const float* Wq   = (const float*)d_in[3];
    const float* Wk   = (const float*)d_in[4];
    const float* Wv   = (const float*)d_in[5];
    const float* Wo   = (const float*)d_in[6];
    float* out = (float*)d_out;

    cudaFuncSetAttribute(flash_kernel,
                         cudaFuncAttributeMaxDynamicSharedMemorySize,
                         FLASH_SMEM_BYTES);
    cudaFuncSetAttribute(gemm_mma<2, NHQ, 0, 0>,
                         cudaFuncAttributeMaxDynamicSharedMemorySize, GEMM_SMEM);
    cudaFuncSetAttribute(gemm_mma<2, NHKV, 1, 1>,
                         cudaFuncAttributeMaxDynamicSharedMemorySize, GEMM_SMEM);
    cudaFuncSetAttribute(gemm_mma<1, NHKV, 2, 2>,
                         cudaFuncAttributeMaxDynamicSharedMemorySize, GEMM_SMEM);
    cudaFuncSetAttribute(gemm_mma<0, 1, 3, 3>,
                         cudaFuncAttributeMaxDynamicSharedMemorySize, GEMM_SMEM);

    // Split-bf16 conversions
    cvt_kernel<0><<<MTOT * KD / 4 / 256, 256>>>(x, MTOT * KD / 4);
    cvt_kernel<1><<<2048 * 2048 / 4 / 256, 256>>>(Wq, 2048 * 2048 / 4);
    cvt_kernel<2><<<512 * 2048 / 4 / 256, 256>>>(Wk, 512 * 2048 / 4);
    cvt_kernel<3><<<512 * 2048 / 4 / 256, 256>>>(Wv, 512 * 2048 / 4);
    cvt_kernel<4><<<2048 * 2048 / 4 / 256, 256>>>(Wo, 2048 * 2048 / 4);

    // Projections on tensor cores (mma.sync, split-bf16 3-pass)
    gemm_mma<2, NHQ, 0, 0><<<dim3(16, 32), 256, GEMM_SMEM>>>(nullptr, cosb, sinb);
    gemm_mma<2, NHKV, 1, 1><<<dim3(4, 32), 256, GEMM_SMEM>>>(nullptr, cosb, sinb);
    gemm_mma<1, NHKV, 2, 2><<<dim3(4, 32), 256, GEMM_SMEM>>>(nullptr, nullptr, nullptr);

    // Attention (fp32)
    flash_kernel<<<dim3(SS / 64, NHQ, BB), 256, FLASH_SMEM_BYTES>>>();

    // y -> split bf16, then output projection
    cvt_kernel<5><<<MTOT * HIDD / 4 / 256, 256>>>(nullptr, MTOT * HIDD / 4);
    gemm_mma<0, 1, 3, 3><<<dim3(16, 32), 256, GEMM_SMEM>>>(out, nullptr, nullptr);
}

// round 4
// speedup vs baseline: 2.0811x; 2.0552x over previous
#include <cuda_runtime.h>
#include <cuda_fp16.h>
#include <cuda_bf16.h>
#include <math.h>
#include <stdint.h>

// Problem constants
#define BB    2
#define SS    2048
#define HIDD  2048
#define NHQ   16
#define NHKV  4
#define HDIM  128
#define KD    2048
#define MTOT  (BB*SS)     // 4096

// ---------------------------------------------------------------------------
// Device-global scratch
// ---------------------------------------------------------------------------
__device__ float g_q[(size_t)BB*NHQ *SS*HDIM];   // [B][H][S][HD] fp32
__device__ float g_k[(size_t)BB*NHKV*SS*HDIM];
__device__ float g_v[(size_t)BB*NHKV*SS*HDIM];

// fp16 operands (g_a16 holds x first, then attention output y)
__device__ __half g_a16 [(size_t)MTOT*KD];
__device__ __half g_wq16[(size_t)2048*2048];
__device__ __half g_wk16[(size_t)512*2048];
__device__ __half g_wv16[(size_t)512*2048];
__device__ __half g_wo16[(size_t)2048*2048];

// ---------------------------------------------------------------------------
__device__ __forceinline__ uint32_t smem_u32(const void* p) {
    uint32_t a;
    asm("{ .reg .u64 t; cvta.to.shared.u64 t, %1; cvt.u32.u64 %0, t; }"
        : "=r"(a) : "l"(p));
    return a;
}

#define LDM4(r0, r1, r2, r3, addr) \
    asm volatile("ldmatrix.sync.aligned.m8n8.x4.shared.b16 {%0,%1,%2,%3}, [%4];" \
                 : "=r"(r0), "=r"(r1), "=r"(r2), "=r"(r3) : "r"(addr))

#define MMA16816(acc, a, b) \
    asm volatile("mma.sync.aligned.m16n8k16.row.col.f32.f16.f16.f32 " \
                 "{%0,%1,%2,%3},{%4,%5,%6,%7},{%8,%9},{%0,%1,%2,%3};" \
                 : "+f"((acc)[0]), "+f"((acc)[1]), "+f"((acc)[2]), "+f"((acc)[3]) \
                 : "r"((a)[0]), "r"((a)[1]), "r"((a)[2]), "r"((a)[3]), \
                   "r"((b)[0]), "r"((b)[1]))

// 16KB tile: 128 rows x 128B (64 halfs). Swizzled for conflict-free ldmatrix.
__device__ __forceinline__ uint32_t tile_off(int row, int ch) {
    return (uint32_t)(row * 128 + ((ch ^ (row & 7)) << 4));
}

// ---------------------------------------------------------------------------
// fp32 -> fp16 conversions. DST: 0=x->a16, 1=Wq, 2=Wk, 3=Wv, 4=Wo
// ---------------------------------------------------------------------------
template<int DST>
__global__ void cvt16(const float* __restrict__ src, int n4)
{
    int i = blockIdx.x * 256 + threadIdx.x;
    if (i >= n4) return;
    __half* dst =
        (DST == 0) ? g_a16 : (DST == 1) ? g_wq16 :
        (DST == 2) ? g_wk16 : (DST == 3) ? g_wv16 : g_wo16;
    float4 v = ((const float4*)src)[i];
    ((__half2*)dst)[2 * i]     = __floats2half2_rn(v.x, v.y);
    ((__half2*)dst)[2 * i + 1] = __floats2half2_rn(v.z, v.w);
}

// ---------------------------------------------------------------------------
// Single-pass fp16 GEMM: C[128x128] = A[M,K] * W[N,K]^T
// 8 warps (2m x 4n), warp tile 64x32, BK=64, 2-stage cp.async pipeline.
// FUSED=1: QKV fused (blockIdx.x: 0-15 Q+rope, 16-19 K+rope, 20-23 V)
// FUSED=0: output projection, plain store to out_param.
// ---------------------------------------------------------------------------
#define GEMM_SMEM (2 * 32768)   // 2 stages x (A 16KB + W 16KB)

template<int FUSED>
__global__ __launch_bounds__(256, 1)
void gemm_f16(float* __restrict__ out_param,
              const float* __restrict__ cosb, const float* __restrict__ sinb)
{
    extern __shared__ __align__(128) char smem[];
    const uint32_t sb = smem_u32(smem);
    const int tid = threadIdx.x, wid = tid >> 5, lane = tid & 31;
    const int m0 = blockIdx.y * 128;
    const int m_base = (wid & 1) * 64;
    const int n_base = (wid >> 1) * 32;

    const __half* __restrict__ A = g_a16;
    const __half* __restrict__ Wp;
    float* outp;
    int NH_sel = 0, n_local0 = 0;
    bool rope = false;
    if (FUSED) {
        int bx = blockIdx.x;
        if (bx < 16)      { Wp = g_wq16; outp = g_q; NH_sel = NHQ;  rope = true;  n_local0 = bx * 128; }
        else if (bx < 20) { Wp = g_wk16; outp = g_k; NH_sel = NHKV; rope = true;  n_local0 = (bx - 16) * 128; }
        else              { Wp = g_wv16; outp = g_v; NH_sel = NHKV; rope = false; n_local0 = (bx - 20) * 128; }
    } else {
        Wp = g_wo16; outp = out_param; n_local0 = blockIdx.x * 128;
    }

    float acc[4][4][4];
#pragma unroll
    for (int mi = 0; mi < 4; mi++)
#pragma unroll
        for (int ni = 0; ni < 4; ni++)
#pragma unroll
            for (int q = 0; q < 4; q++) acc[mi][ni][q] = 0.f;

    auto load_stage = [&](int stage, int k0) {
        uint32_t sbase = sb + stage * 32768;
#pragma unroll
        for (int s = 0; s < 8; s++) {
            int idx  = s * 256 + tid;        // 0..2047
            int tile = idx >> 10;            // 0: A, 1: W
            int rem  = idx & 1023;
            int row  = rem >> 3, ch = rem & 7;
            const __half* g = (tile == 0)
                ? A  + (size_t)(m0 + row) * KD + k0 + ch * 8
                : Wp + (size_t)(n_local0 + row) * KD + k0 + ch * 8;
            uint32_t d = sbase + tile * 16384 + tile_off(row, ch);
            asm volatile("cp.async.cg.shared.global [%0], [%1], 16;"
                         :: "r"(d), "l"(g) : "memory");
        }
        asm volatile("cp.async.commit_group;" ::: "memory");
    };

    load_stage(0, 0);

    const int l15 = lane & 15, lh = lane >> 4;
    const int bmat = lane >> 3, br = lane & 7;

    for (int c = 0; c < 32; c++) {             // KD / 64
        if (c < 31) {
            load_stage((c + 1) & 1, (c + 1) * 64);
            asm volatile("cp.async.wait_group 1;" ::: "memory");
        } else {
            asm volatile("cp.async.wait_group 0;" ::: "memory");
        }
        __syncthreads();

        uint32_t stg = sb + (c & 1) * 32768;
        uint32_t tA = stg, tW = stg + 16384;

#pragma unroll
        for (int ks = 0; ks < 4; ks++) {
            uint32_t af[4][4], bf[4][2];
#pragma unroll
            for (int mi = 0; mi < 4; mi++) {
                int row = m_base + mi * 16 + l15;
                LDM4(af[mi][0], af[mi][1], af[mi][2], af[mi][3],
                     tA + tile_off(row, 2 * ks + lh));
            }
#pragma unroll
            for (int ng = 0; ng < 2; ng++) {
                int row = n_base + ng * 16 + ((bmat & 2) << 2) + br;
                uint32_t r0, r1, r2, r3;
                LDM4(r0, r1, r2, r3, tW + tile_off(row, 2 * ks + (bmat & 1)));
                bf[ng * 2][0] = r0;     bf[ng * 2][1] = r1;
                bf[ng * 2 + 1][0] = r2; bf[ng * 2 + 1][1] = r3;
            }
#pragma unroll
            for (int mi = 0; mi < 4; mi++)
#pragma unroll
                for (int ni = 0; ni < 4; ni++)
                    MMA16816(acc[mi][ni], af[mi], bf[ni]);
        }
        __syncthreads();
    }

    // Epilogue
    const int tr = lane >> 2, tc = lane & 3;
#pragma unroll
    for (int mi = 0; mi < 4; mi++) {
#pragma unroll
        for (int ni = 0; ni < 4; ni++) {
            int nloc = n_local0 + n_base + ni * 8 + tc * 2;
#pragma unroll
            for (int half = 0; half < 2; half++) {
                int m = m0 + m_base + mi * 16 + tr + half * 8;
                float e = acc[mi][ni][half * 2];
                float o = acc[mi][ni][half * 2 + 1];
                if (!FUSED) {
                    *(float2*)(outp + (size_t)m * 2048 + nloc) = make_float2(e, o);
                } else {
                    int bb = m >> 11, s = m & 2047;
                    float oe = e, oo = o;
                    if (rope) {
                        int f = (nloc & (HDIM - 1)) >> 1;
                        float cs = cosb[s * 64 + f];
                        float sn = sinb[s * 64 + f];
                        oe = e * cs - o * sn;
                        oo = e * sn + o * cs;
                    }
                    int h = nloc >> 7, d = nloc & (HDIM - 1);
                    *(float2*)(outp + (((size_t)bb * NH_sel + h) * SS + s) * HDIM + d) =
                        make_float2(oe, oo);
                }
            }
        }
    }
}

// ---------------------------------------------------------------------------
// Flash attention, fp32, causal, GQA. Writes y directly as fp16 into g_a16.
// ---------------------------------------------------------------------------
#define FL_QST   0
#define FL_KS    (128*68)
#define FL_VS    (FL_KS + 64*133)
#define FL_PST   (FL_VS + 64*132)
#define FL_M     (FL_PST + 64*68)
#define FL_L     (FL_M + 64)
#define FL_SC    (FL_L + 64)
#define FL_TOTAL (FL_SC + 64)
#define FLASH_SMEM_BYTES (FL_TOTAL * 4)

__global__ __launch_bounds__(256, 1)
void flash_kernel()
{
    extern __shared__ float sm[];
    float* QsT   = sm + FL_QST;
    float* Ks    = sm + FL_KS;
    float* Vs    = sm + FL_VS;
    float* PsT   = sm + FL_PST;
    float* m_sh  = sm + FL_M;
    float* l_sh  = sm + FL_L;
    float* sc_sh = sm + FL_SC;

    const int tid  = threadIdx.x;
    const int trow = tid >> 4;
    const int tcol = tid & 15;
    const int r0   = trow * 4;
    const int kc0  = tcol * 4;
    const int d0   = tcol * 8;

    const int qt = blockIdx.x;
    const int h  = blockIdx.y;
    const int b  = blockIdx.z;
    const int q0 = qt * 64;
    const int kvh = h / (NHQ / NHKV);
    const float scale = 0.08838834764831845f;

    const float* Qg = g_q + (((size_t)b * NHQ + h) * SS + q0) * HDIM;
    const float* Kb = g_k + (((size_t)b * NHKV + kvh) * SS) * HDIM;
    const float* Vb = g_v + (((size_t)b * NHKV + kvh) * SS) * HDIM;

    for (int i = tid; i < 64 * 32; i += 256) {
        int row = i >> 5, c4 = (i & 31) * 4;
        float4 qv = *(const float4*)(Qg + row * HDIM + c4);
        QsT[(c4 + 0) * 68 + row] = qv.x * scale;
        QsT[(c4 + 1) * 68 + row] = qv.y * scale;
        QsT[(c4 + 2) * 68 + row] = qv.z * scale;
        QsT[(c4 + 3) * 68 + row] = qv.w * scale;
    }
    if (tid < 64) { m_sh[tid] = -1e30f; l_sh[tid] = 0.f; }

    float acc[4][8];
#pragma unroll
    for (int i = 0; i < 4; i++)
#pragma unroll
        for (int j = 0; j < 8; j++) acc[i][j] = 0.f;

    const int ntiles = qt + 1;
    for (int t = 0; t < ntiles; ++t) {
        const int k0 = t * 64;
        __syncthreads();
        const float* Kg = Kb + (size_t)k0 * HDIM;
        const float* Vg = Vb + (size_t)k0 * HDIM;
        for (int i = tid; i < 64 * 32; i += 256) {
            int row = i >> 5, c4 = (i & 31) * 4;
            float4 kv = *(const float4*)(Kg + row * HDIM + c4);
            float* kd = &Ks[row * 133 + c4];
            kd[0] = kv.x; kd[1] = kv.y; kd[2] = kv.z; kd[3] = kv.w;
            float4 vv = *(const float4*)(Vg + row * HDIM + c4);
            *(float4*)&Vs[row * 132 + c4] = vv;
        }
        __syncthreads();

        float sv[4][4];
#pragma unroll
        for (int i = 0; i < 4; i++)
#pragma unroll
            for (int j = 0; j < 4; j++) sv[i][j] = 0.f;

#pragma unroll 4
        for (int d = 0; d < 128; d++) {
            float4 a = *(const float4*)(QsT + d * 68 + r0);
            float b0 = Ks[(kc0 + 0) * 133 + d];
            float b1 = Ks[(kc0 + 1) * 133 + d];
            float b2 = Ks[(kc0 + 2) * 133 + d];
            float b3 = Ks[(kc0 + 3) * 133 + d];
            sv[0][0] = fmaf(a.x, b0, sv[0][0]); sv[0][1] = fmaf(a.x, b1, sv[0][1]);
            sv[0][2] = fmaf(a.x, b2, sv[0][2]); sv[0][3] = fmaf(a.x, b3, sv[0][3]);
            sv[1][0] = fmaf(a.y, b0, sv[1][0]); sv[1][1] = fmaf(a.y, b1, sv[1][1]);
            sv[1][2] = fmaf(a.y, b2, sv[1][2]); sv[1][3] = fmaf(a.y, b3, sv[1][3]);
            sv[2][0] = fmaf(a.z, b0, sv[2][0]); sv[2][1] = fmaf(a.z, b1, sv[2][1]);
            sv[2][2] = fmaf(a.z, b2, sv[2][2]); sv[2][3] = fmaf(a.z, b3, sv[2][3]);
            sv[3][0] = fmaf(a.w, b0, sv[3][0]); sv[3][1] = fmaf(a.w, b1, sv[3][1]);
            sv[3][2] = fmaf(a.w, b2, sv[3][2]); sv[3][3] = fmaf(a.w, b3, sv[3][3]);
        }

        if (t == qt) {
#pragma unroll
            for (int i = 0; i < 4; i++)
#pragma unroll
                for (int j = 0; j < 4; j++)
                    if (k0 + kc0 + j > q0 + r0 + i) sv[i][j] = -1e30f;
        }

#pragma unroll
        for (int j = 0; j < 4; j++)
#pragma unroll
            for (int i = 0; i < 4; i++)
                PsT[(kc0 + j) * 68 + r0 + i] = sv[i][j];
        __syncthreads();

        {
            int r = tid >> 2, seg = tid & 3;
            float vals[16];
            float mloc = -1e30f;
#pragma unroll
            for (int u = 0; u < 16; u++) {
                vals[u] = PsT[(seg * 16 + u) * 68 + r];
                mloc = fmaxf(mloc, vals[u]);
            }
            mloc = fmaxf(mloc, __shfl_xor_sync(0xffffffffu, mloc, 1));
            mloc = fmaxf(mloc, __shfl_xor_sync(0xffffffffu, mloc, 2));
            float m_old = m_sh[r];
            float m_new = fmaxf(m_old, mloc);
            float sum = 0.f;
#pragma unroll
            for (int u = 0; u < 16; u++) {
                float p = __expf(vals[u] - m_new);
                PsT[(seg * 16 + u) * 68 + r] = p;
                sum += p;
            }
            sum += __shfl_xor_sync(0xffffffffu, sum, 1);
            sum += __shfl_xor_sync(0xffffffffu, sum, 2);
            if (seg == 0) {
                float scl = __expf(m_old - m_new);
                m_sh[r]  = m_new;
                l_sh[r]  = l_sh[r] * scl + sum;
                sc_sh[r] = scl;
            }
        }
        __syncthreads();

        {
            float scl[4];
#pragma unroll
            for (int i = 0; i < 4; i++) scl[i] = sc_sh[r0 + i];
#pragma unroll
            for (int i = 0; i < 4; i++)
#pragma unroll
                for (int j = 0; j < 8; j++) acc[i][j] *= scl[i];

#pragma unroll 4
            for (int kk = 0; kk < 64; kk++) {
                float4 a  = *(const float4*)(PsT + kk * 68 + r0);
                float4 v0 = *(const float4*)(Vs + kk * 132 + d0);
                float4 v1 = *(const float4*)(Vs + kk * 132 + d0 + 4);
                float bv[8] = {v0.x, v0.y, v0.z, v0.w, v1.x, v1.y, v1.z, v1.w};
                float av[4] = {a.x, a.y, a.z, a.w};
#pragma unroll
                for (int i = 0; i < 4; i++)
#pragma unroll
                    for (int j = 0; j < 8; j++)
                        acc[i][j] = fmaf(av[i], bv[j], acc[i][j]);
            }
        }
    }

    // Epilogue: normalize, write y as fp16 into g_a16 [B][S][HID]
#pragma unroll
    for (int i = 0; i < 4; i++) {
        int r = r0 + i;
        float inv = 1.f / l_sh[r];
        __half2* op = (__half2*)(g_a16 + ((size_t)b * SS + q0 + r) * HIDD
                                 + h * HDIM + d0);
        op[0] = __floats2half2_rn(acc[i][0] * inv, acc[i][1] * inv);
        op[1] = __floats2half2_rn(acc[i][2] * inv, acc[i][3] * inv);
        op[2] = __floats2half2_rn(acc[i][4] * inv, acc[i][5] * inv);
        op[3] = __floats2half2_rn(acc[i][6] * inv, acc[i][7] * inv);
    }
}

// ---------------------------------------------------------------------------
extern "C" void kernel_launch(void* const* d_in, const int* in_sizes, int n_in,
                              void* d_out, int out_size)
{
    const float* x    = (const float*)d_in[0];
    const float* cosb = (const float*)d_in[1];
    const float* sinb = (const float*)d_in[2];
    const float* Wq   = (const float*)d_in[3];
    const float* Wk   = (const float*)d_in[4];
    const float* Wv   = (const float*)d_in[5];
    const float* Wo   = (const float*)d_in[6];
    float* out = (float*)d_out;

    cudaFuncSetAttribute(flash_kernel,
                         cudaFuncAttributeMaxDynamicSharedMemorySize,
                         FLASH_SMEM_BYTES);
    cudaFuncSetAttribute(gemm_f16<1>,
                         cudaFuncAttributeMaxDynamicSharedMemorySize, GEMM_SMEM);
    cudaFuncSetAttribute(gemm_f16<0>,
                         cudaFuncAttributeMaxDynamicSharedMemorySize, GEMM_SMEM);

    // fp16 conversions
    cvt16<0><<<MTOT * KD / 4 / 256, 256>>>(x, MTOT * KD / 4);
    cvt16<1><<<2048 * 2048 / 4 / 256, 256>>>(Wq, 2048 * 2048 / 4);
    cvt16<2><<<512 * 2048 / 4 / 256, 256>>>(Wk, 512 * 2048 / 4);
    cvt16<3><<<512 * 2048 / 4 / 256, 256>>>(Wv, 512 * 2048 / 4);
    cvt16<4><<<2048 * 2048 / 4 / 256, 256>>>(Wo, 2048 * 2048 / 4);

    // Fused QKV projection (+RoPE for Q,K)
    gemm_f16<1><<<dim3(24, 32), 256, GEMM_SMEM>>>(nullptr, cosb, sinb);

    // Attention (fp32), writes y fp16 into g_a16
    flash_kernel<<<dim3(SS / 64, NHQ, BB), 256, FLASH_SMEM_BYTES>>>();

    // Output projection
    gemm_f16<0><<<dim3(16, 32), 256, GEMM_SMEM>>>(out, nullptr, nullptr);
}

// round 5
// speedup vs baseline: 8.1283x; 3.9058x over previous
#include <cuda_runtime.h>
#include <cuda_fp16.h>
#include <math.h>
#include <stdint.h>

// Problem constants
#define BB    2
#define SS    2048
#define HIDD  2048
#define NHQ   16
#define NHKV  4
#define HDIM  128
#define KD    2048
#define MTOT  (BB*SS)     // 4096

// ---------------------------------------------------------------------------
// Device-global scratch
// ---------------------------------------------------------------------------
__device__ __half g_q16[(size_t)BB*NHQ *SS*HDIM];   // [B][H][S][HD]
__device__ __half g_k16[(size_t)BB*NHKV*SS*HDIM];
__device__ __half g_v16[(size_t)BB*NHKV*SS*HDIM];

// fp16 operands (g_a16 holds x first, then attention output y)
__device__ __half g_a16 [(size_t)MTOT*KD];
__device__ __half g_wq16[(size_t)2048*2048];
__device__ __half g_wk16[(size_t)512*2048];
__device__ __half g_wv16[(size_t)512*2048];
__device__ __half g_wo16[(size_t)2048*2048];

// ---------------------------------------------------------------------------
__device__ __forceinline__ uint32_t smem_u32(const void* p) {
    uint32_t a;
    asm("{ .reg .u64 t; cvta.to.shared.u64 t, %1; cvt.u32.u64 %0, t; }"
        : "=r"(a) : "l"(p));
    return a;
}

#define LDM4(r0, r1, r2, r3, addr) \
    asm volatile("ldmatrix.sync.aligned.m8n8.x4.shared.b16 {%0,%1,%2,%3}, [%4];" \
                 : "=r"(r0), "=r"(r1), "=r"(r2), "=r"(r3) : "r"(addr))

#define LDM4T(r0, r1, r2, r3, addr) \
    asm volatile("ldmatrix.sync.aligned.m8n8.x4.trans.shared.b16 {%0,%1,%2,%3}, [%4];" \
                 : "=r"(r0), "=r"(r1), "=r"(r2), "=r"(r3) : "r"(addr))

#define MMA16816(acc, a, b) \
    asm volatile("mma.sync.aligned.m16n8k16.row.col.f32.f16.f16.f32 " \
                 "{%0,%1,%2,%3},{%4,%5,%6,%7},{%8,%9},{%0,%1,%2,%3};" \
                 : "+f"((acc)[0]), "+f"((acc)[1]), "+f"((acc)[2]), "+f"((acc)[3]) \
                 : "r"((a)[0]), "r"((a)[1]), "r"((a)[2]), "r"((a)[3]), \
                   "r"((b)[0]), "r"((b)[1]))

__device__ __forceinline__ uint32_t ex2_f16x2(uint32_t x) {
    uint32_t r;
    asm volatile("ex2.approx.f16x2 %0, %1;" : "=r"(r) : "r"(x));
    return r;
}
__device__ __forceinline__ float ex2f(float x) {
    float r;
    asm volatile("ex2.approx.f32 %0, %1;" : "=f"(r) : "f"(x));
    return r;
}

// 128B-wide tile (64 halfs/row), swizzled for conflict-free ldmatrix
__device__ __forceinline__ uint32_t tile_off(int row, int ch) {
    return (uint32_t)(row * 128 + ((ch ^ (row & 7)) << 4));
}

__device__ __forceinline__ void cpa16(uint32_t d, const void* s) {
    asm volatile("cp.async.cg.shared.global [%0], [%1], 16;"
                 :: "r"(d), "l"(s) : "memory");
}

// ---------------------------------------------------------------------------
// fp32 -> fp16 conversions. DST: 0=x->a16, 1=Wq, 2=Wk, 3=Wv, 4=Wo
// ---------------------------------------------------------------------------
template<int DST>
__global__ void cvt16(const float* __restrict__ src, int n4)
{
    int i = blockIdx.x * 256 + threadIdx.x;
    if (i >= n4) return;
    __half* dst =
        (DST == 0) ? g_a16 : (DST == 1) ? g_wq16 :
        (DST == 2) ? g_wk16 : (DST == 3) ? g_wv16 : g_wo16;
    float4 v = ((const float4*)src)[i];
    ((__half2*)dst)[2 * i]     = __floats2half2_rn(v.x, v.y);
    ((__half2*)dst)[2 * i + 1] = __floats2half2_rn(v.z, v.w);
}

// ---------------------------------------------------------------------------
// fp16 GEMM: C[128x128] = A[M,K] * W[N,K]^T (8 warps, warp tile 64x32, BK=64)
// FUSED=1: QKV fused (bx 0-15 Q+rope, 16-19 K+rope, 20-23 V), writes fp16.
// FUSED=0: output projection, fp32 store to out_param.
// ---------------------------------------------------------------------------
#define GEMM_SMEM (2 * 32768)

template<int FUSED>
__global__ __launch_bounds__(256, 1)
void gemm_f16(float* __restrict__ out_param,
              const float* __restrict__ cosb, const float* __restrict__ sinb)
{
    extern __shared__ __align__(128) char smem[];
    const uint32_t sb = smem_u32(smem);
    const int tid = threadIdx.x, wid = tid >> 5, lane = tid & 31;
    const int m0 = blockIdx.y * 128;
    const int m_base = (wid & 1) * 64;
    const int n_base = (wid >> 1) * 32;

    const __half* __restrict__ A = g_a16;
    const __half* __restrict__ Wp;
    float* outp = out_param;
    __half* outh = nullptr;
    int NH_sel = 0, n_local0 = 0;
    bool rope = false;
    if (FUSED) {
        int bx = blockIdx.x;
        if (bx < 16)      { Wp = g_wq16; outh = g_q16; NH_sel = NHQ;  rope = true;  n_local0 = bx * 128; }
        else if (bx < 20) { Wp = g_wk16; outh = g_k16; NH_sel = NHKV; rope = true;  n_local0 = (bx - 16) * 128; }
        else              { Wp = g_wv16; outh = g_v16; NH_sel = NHKV; rope = false; n_local0 = (bx - 20) * 128; }
    } else {
        Wp = g_wo16; n_local0 = blockIdx.x * 128;
    }

    float acc[4][4][4];
#pragma unroll
    for (int mi = 0; mi < 4; mi++)
#pragma unroll
        for (int ni = 0; ni < 4; ni++)
#pragma unroll
            for (int q = 0; q < 4; q++) acc[mi][ni][q] = 0.f;

    auto load_stage = [&](int stage, int k0) {
        uint32_t sbase = sb + stage * 32768;
#pragma unroll
        for (int s = 0; s < 8; s++) {
            int idx  = s * 256 + tid;
            int tile = idx >> 10;
            int rem  = idx & 1023;
            int row  = rem >> 3, ch = rem & 7;
            const __half* g = (tile == 0)
                ? A  + (size_t)(m0 + row) * KD + k0 + ch * 8
                : Wp + (size_t)(n_local0 + row) * KD + k0 + ch * 8;
            cpa16(sbase + tile * 16384 + tile_off(row, ch), g);
        }
        asm volatile("cp.async.commit_group;" ::: "memory");
    };

    load_stage(0, 0);

    const int l15 = lane & 15, lh = lane >> 4;
    const int bmat = lane >> 3, br = lane & 7;

    for (int c = 0; c < 32; c++) {
        if (c < 31) {
            load_stage((c + 1) & 1, (c + 1) * 64);
            asm volatile("cp.async.wait_group 1;" ::: "memory");
        } else {
            asm volatile("cp.async.wait_group 0;" ::: "memory");
        }
        __syncthreads();

        uint32_t stg = sb + (c & 1) * 32768;
        uint32_t tA = stg, tW = stg + 16384;

#pragma unroll
        for (int ks = 0; ks < 4; ks++) {
            uint32_t af[4][4], bf[4][2];
#pragma unroll
            for (int mi = 0; mi < 4; mi++) {
                int row = m_base + mi * 16 + l15;
                LDM4(af[mi][0], af[mi][1], af[mi][2], af[mi][3],
                     tA + tile_off(row, 2 * ks + lh));
            }
#pragma unroll
            for (int ng = 0; ng < 2; ng++) {
                int row = n_base + ng * 16 + ((bmat & 2) << 2) + br;
                uint32_t r0, r1, r2, r3;
                LDM4(r0, r1, r2, r3, tW + tile_off(row, 2 * ks + (bmat & 1)));
                bf[ng * 2][0] = r0;     bf[ng * 2][1] = r1;
                bf[ng * 2 + 1][0] = r2; bf[ng * 2 + 1][1] = r3;
            }
#pragma unroll
            for (int mi = 0; mi < 4; mi++)
#pragma unroll
                for (int ni = 0; ni < 4; ni++)
                    MMA16816(acc[mi][ni], af[mi], bf[ni]);
        }
        __syncthreads();
    }

    const int tr = lane >> 2, tc = lane & 3;
#pragma unroll
    for (int mi = 0; mi < 4; mi++) {
#pragma unroll
        for (int ni = 0; ni < 4; ni++) {
            int nloc = n_local0 + n_base + ni * 8 + tc * 2;
#pragma unroll
            for (int half = 0; half < 2; half++) {
                int m = m0 + m_base + mi * 16 + tr + half * 8;
                float e = acc[mi][ni][half * 2];
                float o = acc[mi][ni][half * 2 + 1];
                if (!FUSED) {
                    *(float2*)(outp + (size_t)m * 2048 + nloc) = make_float2(e, o);
                } else {
                    int bb = m >> 11, s = m & 2047;
                    float oe = e, oo = o;
                    if (rope) {
                        int f = (nloc & (HDIM - 1)) >> 1;
                        float cs = cosb[s * 64 + f];
                        float sn = sinb[s * 64 + f];
                        oe = e * cs - o * sn;
                        oo = e * sn + o * cs;
                    }
                    int h = nloc >> 7, d = nloc & (HDIM - 1);
                    *(__half2*)(outh + (((size_t)bb * NH_sel + h) * SS + s) * HDIM + d) =
                        __floats2half2_rn(oe, oo);
                }
            }
        }
    }
}

// ---------------------------------------------------------------------------
// Tensor-core flash attention: fp16 MMA, fp32 accum, ex2.approx.f16x2 softmax.
// BQ=128, BK=64, HD=128. 8 warps, warp = 16 q-rows. Causal, GQA.
// smem: Q 2x16KB | stage0: K 2x8KB, V 2x8KB | stage1: same   = 96KB
// ---------------------------------------------------------------------------
#define FLASH_SMEM 98304
#define C_EXP 0.12753102f    // (1/sqrt(128)) * log2(e)

__global__ __launch_bounds__(256, 1)
void flash16()
{
    extern __shared__ __align__(128) char fsm[];
    const uint32_t sb = smem_u32(fsm);
    const uint32_t sQ = sb;

    const int tid = threadIdx.x, wid = tid >> 5, lane = tid & 31;
    const int l15 = lane & 15, lh = lane >> 4;
    const int bmat = lane >> 3, br = lane & 7;
    const int tr = lane >> 2, tc = lane & 3;
    const int mrow = wid * 16;

    const int qti = (int)gridDim.x - 1 - (int)blockIdx.x;   // big tiles first
    const int h = blockIdx.y, b = blockIdx.z;
    const int q0 = qti * 128;
    const int kvh = h >> 2;

    const __half* Qg = g_q16 + (((size_t)b * NHQ + h) * SS + q0) * HDIM;
    const __half* Kg = g_k16 + (((size_t)b * NHKV + kvh) * SS) * HDIM;
    const __half* Vg = g_v16 + (((size_t)b * NHKV + kvh) * SS) * HDIM;

    // Load Q (128 rows x 128 halfs) into two swizzled 64-half-wide tiles
#pragma unroll
    for (int i = 0; i < 8; i++) {
        int idx = i * 256 + tid;
        int row = idx >> 4, c = idx & 15;
        cpa16(sQ + (c >> 3) * 16384 + tile_off(row, c & 7),
              Qg + (size_t)row * HDIM + c * 8);
    }

    auto load_kv = [&](int st, int t) {
        uint32_t base = sb + 32768 + st * 32768;
        int k0 = t * 64;
#pragma unroll
        for (int i = 0; i < 4; i++) {
            int idx = i * 256 + tid;
            int row = idx >> 4, c = idx & 15;
            uint32_t off = (c >> 3) * 8192 + tile_off(row, c & 7);
            const __half* kg = Kg + (size_t)(k0 + row) * HDIM + c * 8;
            const __half* vg = Vg + (size_t)(k0 + row) * HDIM + c * 8;
            cpa16(base + off, kg);
            cpa16(base + 16384 + off, vg);
        }
        asm volatile("cp.async.commit_group;" ::: "memory");
    };

    load_kv(0, 0);
    asm volatile("cp.async.commit_group;" ::: "memory");  // close Q+KV0 group

    float m0v = -1e30f, m1v = -1e30f, l0 = 0.f, l1 = 0.f;
    float y[16][4];
#pragma unroll
    for (int i = 0; i < 16; i++)
#pragma unroll
        for (int q = 0; q < 4; q++) y[i][q] = 0.f;

    const int nt = 2 * qti + 2;
    for (int t = 0; t < nt; t++) {
        if (t + 1 < nt) {
            load_kv((t + 1) & 1, t + 1);
            asm volatile("cp.async.wait_group 1;" ::: "memory");
        } else {
            asm volatile("cp.async.wait_group 0;" ::: "memory");
        }
        __syncthreads();

        uint32_t stg = sb + 32768 + (t & 1) * 32768;
        uint32_t sK = stg, sV = stg + 16384;
        const int k0 = t * 64;

        // ---- S = Q K^T (raw scores, scale folded into exponent) ----
        float S[8][4];
#pragma unroll
        for (int ni = 0; ni < 8; ni++)
#pragma unroll
            for (int q = 0; q < 4; q++) S[ni][q] = 0.f;

#pragma unroll
        for (int kc = 0; kc < 8; kc++) {
            uint32_t a[4];
            LDM4(a[0], a[1], a[2], a[3],
                 sQ + (kc >> 2) * 16384 + tile_off(mrow + l15, 2 * (kc & 3) + lh));
#pragma unroll
            for (int ng = 0; ng < 4; ng++) {
                uint32_t r0, r1, r2, r3;
                LDM4(r0, r1, r2, r3,
                     sK + (kc >> 2) * 8192 +
                     tile_off(ng * 16 + ((bmat & 2) << 2) + br, 2 * (kc & 3) + (bmat & 1)));
                uint32_t b0[2] = { r0, r1 }, b1[2] = { r2, r3 };
                MMA16816(S[ng * 2], a, b0);
                MMA16816(S[ng * 2 + 1], a, b1);
            }
        }

        // ---- causal mask (only the last two tiles can be partial) ----
        if (k0 + 63 > q0) {
            int row0 = q0 + mrow + tr, row1 = row0 + 8;
#pragma unroll
            for (int ni = 0; ni < 8; ni++) {
                int col = k0 + ni * 8 + 2 * tc;
                if (col > row0)     S[ni][0] = -1e30f;
                if (col + 1 > row0) S[ni][1] = -1e30f;
                if (col > row1)     S[ni][2] = -1e30f;
                if (col + 1 > row1) S[ni][3] = -1e30f;
            }
        }

        // ---- online softmax (per-row, within quad) ----
        float mx0 = -1e30f, mx1 = -1e30f;
#pragma unroll
        for (int ni = 0; ni < 8; ni++) {
            mx0 = fmaxf(mx0, fmaxf(S[ni][0], S[ni][1]));
            mx1 = fmaxf(mx1, fmaxf(S[ni][2], S[ni][3]));
        }
        mx0 = fmaxf(mx0, __shfl_xor_sync(0xffffffffu, mx0, 1));
        mx0 = fmaxf(mx0, __shfl_xor_sync(0xffffffffu, mx0, 2));
        mx1 = fmaxf(mx1, __shfl_xor_sync(0xffffffffu, mx1, 1));
        mx1 = fmaxf(mx1, __shfl_xor_sync(0xffffffffu, mx1, 2));

        float mn0 = fmaxf(m0v, mx0), mn1 = fmaxf(m1v, mx1);
        float f0 = ex2f((m0v - mn0) * C_EXP);
        float f1 = ex2f((m1v - mn1) * C_EXP);
        m0v = mn0; m1v = mn1;

        uint32_t P[8][2];
        float s0 = 0.f, s1 = 0.f;
#pragma unroll
        for (int ni = 0; ni < 8; ni++) {
            __half2 h0 = __floats2half2_rn((S[ni][0] - mn0) * C_EXP,
                                           (S[ni][1] - mn0) * C_EXP);
            __half2 h1 = __floats2half2_rn((S[ni][2] - mn1) * C_EXP,
                                           (S[ni][3] - mn1) * C_EXP);
            uint32_t p0 = ex2_f16x2(*(uint32_t*)&h0);
            uint32_t p1 = ex2_f16x2(*(uint32_t*)&h1);
            P[ni][0] = p0; P[ni][1] = p1;
            float2 q0f = __half22float2(*(__half2*)&p0);
            float2 q1f = __half22float2(*(__half2*)&p1);
            s0 += q0f.x + q0f.y;
            s1 += q1f.x + q1f.y;
        }
        s0 += __shfl_xor_sync(0xffffffffu, s0, 1);
        s0 += __shfl_xor_sync(0xffffffffu, s0, 2);
        s1 += __shfl_xor_sync(0xffffffffu, s1, 1);
        s1 += __shfl_xor_sync(0xffffffffu, s1, 2);
        l0 = l0 * f0 + s0;
        l1 = l1 * f1 + s1;

#pragma unroll
        for (int i = 0; i < 16; i++) {
            y[i][0] *= f0; y[i][1] *= f0;
            y[i][2] *= f1; y[i][3] *= f1;
        }

        // ---- y += P V ----
#pragma unroll
        for (int kc2 = 0; kc2 < 4; kc2++) {
            uint32_t a[4] = { P[2 * kc2][0], P[2 * kc2][1],
                              P[2 * kc2 + 1][0], P[2 * kc2 + 1][1] };
#pragma unroll
            for (int dj = 0; dj < 8; dj++) {
                uint32_t r0, r1, r2, r3;
                LDM4T(r0, r1, r2, r3,
                      sV + (dj >> 2) * 8192 +
                      tile_off(kc2 * 16 + l15, ((dj & 3) << 1) + lh));
                uint32_t b0[2] = { r0, r1 }, b1[2] = { r2, r3 };
                MMA16816(y[2 * dj], a, b0);
                MMA16816(y[2 * dj + 1], a, b1);
            }
        }
        __syncthreads();
    }

    // ---- epilogue: normalize, write y fp16 into g_a16 [B][S][HID] ----
    float inv0 = 1.f / l0, inv1 = 1.f / l1;
#pragma unroll
    for (int ni = 0; ni < 16; ni++) {
        int col = h * HDIM + ni * 8 + 2 * tc;
        int row0 = q0 + mrow + tr;
        *(__half2*)(g_a16 + ((size_t)b * SS + row0) * HIDD + col) =
            __floats2half2_rn(y[ni][0] * inv0, y[ni][1] * inv0);
        *(__half2*)(g_a16 + ((size_t)b * SS + row0 + 8) * HIDD + col) =
            __floats2half2_rn(y[ni][2] * inv1, y[ni][3] * inv1);
    }
}

// ---------------------------------------------------------------------------
extern "C" void kernel_launch(void* const* d_in, const int* in_sizes, int n_in,
                              void* d_out, int out_size)
{
    const float* x    = (const float*)d_in[0];
    const float* cosb = (const float*)d_in[1];
    const float* sinb = (const float*)d_in[2];
    const float* Wq   = (const float*)d_in[3];
    const float* Wk   = (const float*)d_in[4];
    const float* Wv   = (const float*)d_in[5];
    const float* Wo   = (const float*)d_in[6];
    float* out = (float*)d_out;

    cudaFuncSetAttribute(flash16,
                         cudaFuncAttributeMaxDynamicSharedMemorySize, FLASH_SMEM);
    cudaFuncSetAttribute(gemm_f16<1>,
                         cudaFuncAttributeMaxDynamicSharedMemorySize, GEMM_SMEM);
    cudaFuncSetAttribute(gemm_f16<0>,
                         cudaFuncAttributeMaxDynamicSharedMemorySize, GEMM_SMEM);

    // fp16 conversions
    cvt16<0><<<MTOT * KD / 4 / 256, 256>>>(x, MTOT * KD / 4);
    cvt16<1><<<2048 * 2048 / 4 / 256, 256>>>(Wq, 2048 * 2048 / 4);
    cvt16<2><<<512 * 2048 / 4 / 256, 256>>>(Wk, 512 * 2048 / 4);
    cvt16<3><<<512 * 2048 / 4 / 256, 256>>>(Wv, 512 * 2048 / 4);
    cvt16<4><<<2048 * 2048 / 4 / 256, 256>>>(Wo, 2048 * 2048 / 4);

    // Fused QKV projection (+RoPE), fp16 outputs
    gemm_f16<1><<<dim3(24, 32), 256, GEMM_SMEM>>>(nullptr, cosb, sinb);

    // Tensor-core flash attention
    flash16<<<dim3(SS / 128, NHQ, BB), 256, FLASH_SMEM>>>();

    // Output projection (fp32 out)
    gemm_f16<0><<<dim3(16, 32), 256, GEMM_SMEM>>>(out, nullptr, nullptr);
}

// round 6
// speedup vs baseline: 9.1218x; 1.1222x over previous
#include <cuda_runtime.h>
#include <cuda_fp16.h>
#include <math.h>
#include <stdint.h>

// Problem constants
#define BB    2
#define SS    2048
#define HIDD  2048
#define NHQ   16
#define NHKV  4
#define HDIM  128
#define KD    2048
#define MTOT  (BB*SS)     // 4096

// ---------------------------------------------------------------------------
// Device-global scratch
// ---------------------------------------------------------------------------
__device__ __half g_q16[(size_t)BB*NHQ *SS*HDIM];   // [B][H][S][HD]
__device__ __half g_k16[(size_t)BB*NHKV*SS*HDIM];
__device__ __half g_v16[(size_t)BB*NHKV*SS*HDIM];

__device__ __half g_a16 [(size_t)MTOT*KD];          // x, then y
__device__ __half g_wq16[(size_t)2048*2048];
__device__ __half g_wk16[(size_t)512*2048];
__device__ __half g_wv16[(size_t)512*2048];
__device__ __half g_wo16[(size_t)2048*2048];

// ---------------------------------------------------------------------------
__device__ __forceinline__ uint32_t smem_u32(const void* p) {
    uint32_t a;
    asm("{ .reg .u64 t; cvta.to.shared.u64 t, %1; cvt.u32.u64 %0, t; }"
        : "=r"(a) : "l"(p));
    return a;
}

#define LDM4(r0, r1, r2, r3, addr) \
    asm volatile("ldmatrix.sync.aligned.m8n8.x4.shared.b16 {%0,%1,%2,%3}, [%4];" \
                 : "=r"(r0), "=r"(r1), "=r"(r2), "=r"(r3) : "r"(addr))

#define LDM4T(r0, r1, r2, r3, addr) \
    asm volatile("ldmatrix.sync.aligned.m8n8.x4.trans.shared.b16 {%0,%1,%2,%3}, [%4];" \
                 : "=r"(r0), "=r"(r1), "=r"(r2), "=r"(r3) : "r"(addr))

#define MMA16816(acc, a, b) \
    asm volatile("mma.sync.aligned.m16n8k16.row.col.f32.f16.f16.f32 " \
                 "{%0,%1,%2,%3},{%4,%5,%6,%7},{%8,%9},{%0,%1,%2,%3};" \
                 : "+f"((acc)[0]), "+f"((acc)[1]), "+f"((acc)[2]), "+f"((acc)[3]) \
                 : "r"((a)[0]), "r"((a)[1]), "r"((a)[2]), "r"((a)[3]), \
                   "r"((b)[0]), "r"((b)[1]))

__device__ __forceinline__ uint32_t ex2_f16x2(uint32_t x) {
    uint32_t r;
    asm volatile("ex2.approx.f16x2 %0, %1;" : "=r"(r) : "r"(x));
    return r;
}
__device__ __forceinline__ float ex2f(float x) {
    float r;
    asm volatile("ex2.approx.f32 %0, %1;" : "=f"(r) : "f"(x));
    return r;
}

// 128B-wide tile (64 halfs/row), swizzled for conflict-free ldmatrix
__device__ __forceinline__ uint32_t tile_off(int row, int ch) {
    return (uint32_t)(row * 128 + ((ch ^ (row & 7)) << 4));
}

__device__ __forceinline__ void cpa16(uint32_t d, const void* s) {
    asm volatile("cp.async.cg.shared.global [%0], [%1], 16;"
                 :: "r"(d), "l"(s) : "memory");
}

// ---------------------------------------------------------------------------
// Fused fp32 -> fp16 conversion of x + all four weights, one launch.
// segments (in float4 units): x 2097152 | Wq 1048576 | Wk 262144 | Wv 262144 | Wo 1048576
// ---------------------------------------------------------------------------
#define CVT_N4 4718592

__global__ void cvt_all(const float* __restrict__ x,  const float* __restrict__ wq,
                        const float* __restrict__ wk, const float* __restrict__ wv,
                        const float* __restrict__ wo)
{
    int i = blockIdx.x * 256 + threadIdx.x;
    if (i >= CVT_N4) return;
    const float4* s;
    __half2* d;
    int off;
    if (i < 2097152)      { s = (const float4*)x;  d = (__half2*)g_a16;  off = i; }
    else if (i < 3145728) { s = (const float4*)wq; d = (__half2*)g_wq16; off = i - 2097152; }
    else if (i < 3407872) { s = (const float4*)wk; d = (__half2*)g_wk16; off = i - 3145728; }
    else if (i < 3670016) { s = (const float4*)wv; d = (__half2*)g_wv16; off = i - 3407872; }
    else                  { s = (const float4*)wo; d = (__half2*)g_wo16; off = i - 3670016; }
    float4 v = s[off];
    d[2 * off]     = __floats2half2_rn(v.x, v.y);
    d[2 * off + 1] = __floats2half2_rn(v.z, v.w);
}

// ---------------------------------------------------------------------------
// fp16 GEMM: C[128x256 tile] = A[M,K] * W[N,K]^T
// 8 warps (2m x 4n), warp tile 64x64, BK=64, 3-stage cp.async, 1 sync/iter.
// FUSED=1: QKV fused (bx 0-7 Q+rope, 8-9 K+rope, 10-11 V), fp16 out.
// FUSED=0: output projection, fp32 store.
// ---------------------------------------------------------------------------
#define GEMM_STAGE 49152              // A 16KB + W 32KB
#define GEMM_SMEM  (3 * GEMM_STAGE)   // 147456

template<int FUSED>
__global__ __launch_bounds__(256, 1)
void gemm_f16(float* __restrict__ out_param,
              const float* __restrict__ cosb, const float* __restrict__ sinb)
{
    extern __shared__ __align__(128) char smem[];
    const uint32_t sb = smem_u32(smem);
    const int tid = threadIdx.x, wid = tid >> 5, lane = tid & 31;
    const int m0 = blockIdx.y * 128;
    const int m_base = (wid & 1) * 64;
    const int n_base = (wid >> 1) * 64;

    const __half* __restrict__ A = g_a16;
    const __half* __restrict__ Wp;
    __half* outh = nullptr;
    int NH_sel = 0, n_local0 = 0;
    bool rope = false;
    if (FUSED) {
        int bx = blockIdx.x;
        if (bx < 8)       { Wp = g_wq16; outh = g_q16; NH_sel = NHQ;  rope = true;  n_local0 = bx * 256; }
        else if (bx < 10) { Wp = g_wk16; outh = g_k16; NH_sel = NHKV; rope = true;  n_local0 = (bx - 8) * 256; }
        else              { Wp = g_wv16; outh = g_v16; NH_sel = NHKV; rope = false; n_local0 = (bx - 10) * 256; }
    } else {
        Wp = g_wo16; n_local0 = blockIdx.x * 256;
    }

    float acc[4][8][4];
#pragma unroll
    for (int mi = 0; mi < 4; mi++)
#pragma unroll
        for (int ni = 0; ni < 8; ni++)
#pragma unroll
            for (int q = 0; q < 4; q++) acc[mi][ni][q] = 0.f;

    auto load_stage = [&](int stage, int k0) {
        uint32_t sbase = sb + stage * GEMM_STAGE;
#pragma unroll
        for (int s = 0; s < 12; s++) {
            int idx = s * 256 + tid;           // 0..3071
            if (idx < 1024) {                  // A: 128 rows x 8 chunks
                int row = idx >> 3, ch = idx & 7;
                cpa16(sbase + tile_off(row, ch),
                      A + (size_t)(m0 + row) * KD + k0 + ch * 8);
            } else {                           // W: 256 rows x 8 chunks
                int rem = idx - 1024;
                int row = rem >> 3, ch = rem & 7;
                cpa16(sbase + 16384 + tile_off(row, ch),
                      Wp + (size_t)(n_local0 + row) * KD + k0 + ch * 8);
            }
        }
        asm volatile("cp.async.commit_group;" ::: "memory");
    };

    load_stage(0, 0);
    load_stage(1, 64);

    const int l15 = lane & 15, lh = lane >> 4;
    const int bmat = lane >> 3, br = lane & 7;

    for (int c = 0; c < 32; c++) {
        if (c < 31) asm volatile("cp.async.wait_group 1;" ::: "memory");
        else        asm volatile("cp.async.wait_group 0;" ::: "memory");
        __syncthreads();
        if (c + 2 < 32) {
            int st = (c + 2) % 3;
            load_stage(st, (c + 2) * 64);
        }

        uint32_t stg = sb + (c % 3) * GEMM_STAGE;
        uint32_t tA = stg, tW = stg + 16384;

#pragma unroll
        for (int ks = 0; ks < 4; ks++) {
            uint32_t af[4][4], bf[8][2];
#pragma unroll
            for (int mi = 0; mi < 4; mi++) {
                int row = m_base + mi * 16 + l15;
                LDM4(af[mi][0], af[mi][1], af[mi][2], af[mi][3],
                     tA + tile_off(row, 2 * ks + lh));
            }
#pragma unroll
            for (int ng = 0; ng < 4; ng++) {
                int row = n_base + ng * 16 + ((bmat & 2) << 2) + br;
                uint32_t r0, r1, r2, r3;
                LDM4(r0, r1, r2, r3, tW + tile_off(row, 2 * ks + (bmat & 1)));
                bf[ng * 2][0] = r0;     bf[ng * 2][1] = r1;
                bf[ng * 2 + 1][0] = r2; bf[ng * 2 + 1][1] = r3;
            }
#pragma unroll
            for (int mi = 0; mi < 4; mi++)
#pragma unroll
                for (int ni = 0; ni < 8; ni++)
                    MMA16816(acc[mi][ni], af[mi], bf[ni]);
        }
    }

    const int tr = lane >> 2, tc = lane & 3;
#pragma unroll
    for (int mi = 0; mi < 4; mi++) {
#pragma unroll
        for (int ni = 0; ni < 8; ni++) {
            int nloc = n_local0 + n_base + ni * 8 + tc * 2;
#pragma unroll
            for (int half = 0; half < 2; half++) {
                int m = m0 + m_base + mi * 16 + tr + half * 8;
                float e = acc[mi][ni][half * 2];
                float o = acc[mi][ni][half * 2 + 1];
                if (!FUSED) {
                    *(float2*)(out_param + (size_t)m * 2048 + nloc) = make_float2(e, o);
                } else {
                    int bb = m >> 11, s = m & 2047;
                    float oe = e, oo = o;
                    if (rope) {
                        int f = (nloc & (HDIM - 1)) >> 1;
                        float cs = cosb[s * 64 + f];
                        float sn = sinb[s * 64 + f];
                        oe = e * cs - o * sn;
                        oo = e * sn + o * cs;
                    }
                    int h = nloc >> 7, d = nloc & (HDIM - 1);
                    *(__half2*)(outh + (((size_t)bb * NH_sel + h) * SS + s) * HDIM + d) =
                        __floats2half2_rn(oe, oo);
                }
            }
        }
    }
}

// ---------------------------------------------------------------------------
// Tensor-core flash attention: fp16 MMA, fp32 accum, ex2.approx.f16x2 softmax.
// BQ=128, BK=128, HD=128. 8 warps, warp = 16 q-rows. Causal, GQA.
// smem: Q 32KB | 2 KV stages x (K 32KB + V 32KB) = 160KB
// ---------------------------------------------------------------------------
#define FLASH_SMEM 163840
#define C_EXP 0.12753102f    // (1/sqrt(128)) * log2(e)

__global__ __launch_bounds__(256, 1)
void flash16()
{
    extern __shared__ __align__(128) char fsm[];
    const uint32_t sb = smem_u32(fsm);
    const uint32_t sQ = sb;

    const int tid = threadIdx.x, wid = tid >> 5, lane = tid & 31;
    const int l15 = lane & 15, lh = lane >> 4;
    const int bmat = lane >> 3, br = lane & 7;
    const int tr = lane >> 2, tc = lane & 3;
    const int mrow = wid * 16;

    const int qti = (int)gridDim.x - 1 - (int)blockIdx.x;   // big tiles first
    const int h = blockIdx.y, b = blockIdx.z;
    const int q0 = qti * 128;
    const int kvh = h >> 2;

    const __half* Qg = g_q16 + (((size_t)b * NHQ + h) * SS + q0) * HDIM;
    const __half* Kg = g_k16 + (((size_t)b * NHKV + kvh) * SS) * HDIM;
    const __half* Vg = g_v16 + (((size_t)b * NHKV + kvh) * SS) * HDIM;

    // Q (128 x 128 halfs) into two swizzled 64-wide tiles
#pragma unroll
    for (int i = 0; i < 8; i++) {
        int idx = i * 256 + tid;
        int row = idx >> 4, c = idx & 15;
        cpa16(sQ + (c >> 3) * 16384 + tile_off(row, c & 7),
              Qg + (size_t)row * HDIM + c * 8);
    }

    auto load_kv = [&](int st, int t) {
        uint32_t base = sb + 32768 + st * 65536;
        int k0 = t * 128;
#pragma unroll
        for (int i = 0; i < 16; i++) {
            int idx = i * 256 + tid;            // 0..4095
            int kv  = idx >> 11;                // 0: K, 1: V
            int rem = idx & 2047;
            int row = rem >> 4, c = rem & 15;
            uint32_t off = (c >> 3) * 16384 + tile_off(row, c & 7);
            const __half* g = (kv == 0)
                ? Kg + (size_t)(k0 + row) * HDIM + c * 8
                : Vg + (size_t)(k0 + row) * HDIM + c * 8;
            cpa16(base + kv * 32768 + off, g);
        }
        asm volatile("cp.async.commit_group;" ::: "memory");
    };

    load_kv(0, 0);

    float m0v = -1e30f, m1v = -1e30f, l0 = 0.f, l1 = 0.f;
    float y[16][4];
#pragma unroll
    for (int i = 0; i < 16; i++)
#pragma unroll
        for (int q = 0; q < 4; q++) y[i][q] = 0.f;

    const int nt = qti + 1;
    for (int t = 0; t < nt; t++) {
        if (t + 1 < nt) {
            load_kv((t + 1) & 1, t + 1);
            asm volatile("cp.async.wait_group 1;" ::: "memory");
        } else {
            asm volatile("cp.async.wait_group 0;" ::: "memory");
        }
        __syncthreads();

        uint32_t stg = sb + 32768 + (t & 1) * 65536;
        uint32_t sK = stg, sV = stg + 32768;
        const int k0 = t * 128;

        // ---- S = Q K^T ----
        float S[16][4];
#pragma unroll
        for (int ni = 0; ni < 16; ni++)
#pragma unroll
            for (int q = 0; q < 4; q++) S[ni][q] = 0.f;

#pragma unroll
        for (int kc = 0; kc < 8; kc++) {
            uint32_t a[4];
            LDM4(a[0], a[1], a[2], a[3],
                 sQ + (kc >> 2) * 16384 + tile_off(mrow + l15, 2 * (kc & 3) + lh));
#pragma unroll
            for (int ng = 0; ng < 8; ng++) {
                uint32_t r0, r1, r2, r3;
                LDM4(r0, r1, r2, r3,
                     sK + (kc >> 2) * 16384 +
                     tile_off(ng * 16 + ((bmat & 2) << 2) + br, 2 * (kc & 3) + (bmat & 1)));
                uint32_t b0[2] = { r0, r1 }, b1[2] = { r2, r3 };
                MMA16816(S[ng * 2], a, b0);
                MMA16816(S[ng * 2 + 1], a, b1);
            }
        }

        // ---- causal mask (diagonal tile only) ----
        if (t == nt - 1) {
            int row0 = q0 + mrow + tr, row1 = row0 + 8;
#pragma unroll
            for (int ni = 0; ni < 16; ni++) {
                int col = k0 + ni * 8 + 2 * tc;
                if (col > row0)     S[ni][0] = -1e30f;
                if (col + 1 > row0) S[ni][1] = -1e30f;
                if (col > row1)     S[ni][2] = -1e30f;
                if (col + 1 > row1) S[ni][3] = -1e30f;
            }
        }

        // ---- online softmax ----
        float mx0 = -1e30f, mx1 = -1e30f;
#pragma unroll
        for (int ni = 0; ni < 16; ni++) {
            mx0 = fmaxf(mx0, fmaxf(S[ni][0], S[ni][1]));
            mx1 = fmaxf(mx1, fmaxf(S[ni][2], S[ni][3]));
        }
        mx0 = fmaxf(mx0, __shfl_xor_sync(0xffffffffu, mx0, 1));
        mx0 = fmaxf(mx0, __shfl_xor_sync(0xffffffffu, mx0, 2));
        mx1 = fmaxf(mx1, __shfl_xor_sync(0xffffffffu, mx1, 1));
        mx1 = fmaxf(mx1, __shfl_xor_sync(0xffffffffu, mx1, 2));

        float mn0 = fmaxf(m0v, mx0), mn1 = fmaxf(m1v, mx1);
        float f0 = ex2f((m0v - mn0) * C_EXP);
        float f1 = ex2f((m1v - mn1) * C_EXP);
        m0v = mn0; m1v = mn1;

        uint32_t P[16][2];
        float s0 = 0.f, s1 = 0.f;
#pragma unroll
        for (int ni = 0; ni < 16; ni++) {
            __half2 h0 = __floats2half2_rn((S[ni][0] - mn0) * C_EXP,
                                           (S[ni][1] - mn0) * C_EXP);
            __half2 h1 = __floats2half2_rn((S[ni][2] - mn1) * C_EXP,
                                           (S[ni][3] - mn1) * C_EXP);
            uint32_t p0 = ex2_f16x2(*(uint32_t*)&h0);
            uint32_t p1 = ex2_f16x2(*(uint32_t*)&h1);
            P[ni][0] = p0; P[ni][1] = p1;
            float2 q0f = __half22float2(*(__half2*)&p0);
            float2 q1f = __half22float2(*(__half2*)&p1);
            s0 += q0f.x + q0f.y;
            s1 += q1f.x + q1f.y;
        }
        s0 += __shfl_xor_sync(0xffffffffu, s0, 1);
        s0 += __shfl_xor_sync(0xffffffffu, s0, 2);
        s1 += __shfl_xor_sync(0xffffffffu, s1, 1);
        s1 += __shfl_xor_sync(0xffffffffu, s1, 2);
        l0 = l0 * f0 + s0;
        l1 = l1 * f1 + s1;

#pragma unroll
        for (int i = 0; i < 16; i++) {
            y[i][0] *= f0; y[i][1] *= f0;
            y[i][2] *= f1; y[i][3] *= f1;
        }

        // ---- y += P V ----
#pragma unroll
        for (int kc2 = 0; kc2 < 8; kc2++) {
            uint32_t a[4] = { P[2 * kc2][0], P[2 * kc2][1],
                              P[2 * kc2 + 1][0], P[2 * kc2 + 1][1] };
#pragma unroll
            for (int dj = 0; dj < 8; dj++) {
                uint32_t r0, r1, r2, r3;
                LDM4T(r0, r1, r2, r3,
                      sV + (dj >> 2) * 16384 +
                      tile_off(kc2 * 16 + l15, ((dj & 3) << 1) + lh));
                uint32_t b0[2] = { r0, r1 }, b1[2] = { r2, r3 };
                MMA16816(y[2 * dj], a, b0);
                MMA16816(y[2 * dj + 1], a, b1);
            }
        }
        __syncthreads();
    }

    // ---- epilogue: normalize, write y fp16 into g_a16 [B][S][HID] ----
    float inv0 = 1.f / l0, inv1 = 1.f / l1;
#pragma unroll
    for (int ni = 0; ni < 16; ni++) {
        int col = h * HDIM + ni * 8 + 2 * tc;
        int row0 = q0 + mrow + tr;
        *(__half2*)(g_a16 + ((size_t)b * SS + row0) * HIDD + col) =
            __floats2half2_rn(y[ni][0] * inv0, y[ni][1] * inv0);
        *(__half2*)(g_a16 + ((size_t)b * SS + row0 + 8) * HIDD + col) =
            __floats2half2_rn(y[ni][2] * inv1, y[ni][3] * inv1);
    }
}

// ---------------------------------------------------------------------------
extern "C" void kernel_launch(void* const* d_in, const int* in_sizes, int n_in,
                              void* d_out, int out_size)
{
    const float* x    = (const float*)d_in[0];
    const float* cosb = (const float*)d_in[1];
    const float* sinb = (const float*)d_in[2];
    const float* Wq   = (const float*)d_in[3];
    const float* Wk   = (const float*)d_in[4];
    const float* Wv   = (const float*)d_in[5];
    const float* Wo   = (const float*)d_in[6];
    float* out = (float*)d_out;

    cudaFuncSetAttribute(flash16,
                         cudaFuncAttributeMaxDynamicSharedMemorySize, FLASH_SMEM);
    cudaFuncSetAttribute(gemm_f16<1>,
                         cudaFuncAttributeMaxDynamicSharedMemorySize, GEMM_SMEM);
    cudaFuncSetAttribute(gemm_f16<0>,
                         cudaFuncAttributeMaxDynamicSharedMemorySize, GEMM_SMEM);

    // Fused fp16 conversions (x + all weights)
    cvt_all<<<(CVT_N4 + 255) / 256, 256>>>(x, Wq, Wk, Wv, Wo);

    // Fused QKV projection (+RoPE), fp16 outputs
    gemm_f16<1><<<dim3(12, 32), 256, GEMM_SMEM>>>(nullptr, cosb, sinb);

    // Tensor-core flash attention
    flash16<<<dim3(SS / 128, NHQ, BB), 256, FLASH_SMEM>>>();

    // Output projection (fp32 out)
    gemm_f16<0><<<dim3(8, 32), 256, GEMM_SMEM>>>(out, nullptr, nullptr);
}